// round 9
// baseline (speedup 1.0000x reference)
#include <cuda_runtime.h>
#include <cuda_fp16.h>
#include <math.h>

#define N_NODES 50000
#define N_EDGES 800000
#define NB      64
#define IN_DIM  64
#define HID     128
#define OUT_DIM 64
#define SCAN_BLOCKS 200   // 200*256 = 51200 >= N_NODES

// ---------------- scratch (device globals: no allocs allowed) ----------------
__device__ __align__(16) int    g_degi[N_NODES];
__device__ __align__(16) float  g_dis[N_NODES];
__device__ __align__(16) int    g_rowptr[N_NODES + 1];
__device__ __align__(16) int    g_cursor[N_NODES];
__device__ __align__(16) int    g_csrc[N_EDGES];
__device__ __align__(16) float  g_cw[N_EDGES];
__device__ __align__(16) int    g_bsum[256];
__device__ __align__(16) __half g_x16[(size_t)N_NODES * IN_DIM];  // fp16 copy of x
__device__ __align__(16) __half g_h16[(size_t)N_NODES * HID];     // fp16 layer-1 output
__device__ __align__(16) float  g_bufA[(size_t)N_NODES * HID];    // layer-2 GEMM out (fp32, pooled)
__device__ __align__(16) float  g_bufB[(size_t)N_NODES * HID];    // aggregation target / GEMM input
__device__ __align__(16) float  g_pooled[NB * HID];
__device__ __align__(16) float  g_cnt[NB];

__device__ __forceinline__ void red_v4(float* ap, float a, float b, float c, float d) {
    asm volatile("red.global.add.v4.f32 [%0], {%1,%2,%3,%4};"
                 :: "l"(ap), "f"(a), "f"(b), "f"(c), "f"(d) : "memory");
}

// ---------------- zero: degi=0, pooled=0, cnt=0 ----------------
__global__ void k_zero() {
    int i = blockIdx.x * blockDim.x + threadIdx.x;
    if (i < N_NODES) g_degi[i] = 0;
    if (i < NB * HID) g_pooled[i] = 0.0f;
    if (i < NB) g_cnt[i] = 0.0f;
}

// ---------------- x -> fp16 (independent of CSR build) ----------------
__global__ void k_xcvt(const float* __restrict__ x) {
    int t = blockIdx.x * blockDim.x + threadIdx.x;
    if (t >= N_NODES * (IN_DIM / 2)) return;
    float2 v = reinterpret_cast<const float2*>(x)[t];
    reinterpret_cast<__half2*>(g_x16)[t] = __floats2half2_rn(v.x, v.y);
}

// ---------------- degree counts over dst ----------------
__global__ void k_deg(const int* __restrict__ dst) {
    int e = blockIdx.x * blockDim.x + threadIdx.x;
    if (e < N_EDGES) atomicAdd(&g_degi[dst[e]], 1);
}

// ---------------- 2-level exclusive scan of degi -> rowptr ----------------
__global__ __launch_bounds__(256) void k_scan_part() {
    __shared__ int sm[256];
    int b = blockIdx.x, t = threadIdx.x;
    int i = b * 256 + t;
    int v = (i < N_NODES) ? g_degi[i] : 0;
    sm[t] = v;
    __syncthreads();
#pragma unroll
    for (int off = 1; off < 256; off <<= 1) {
        int u = (t >= off) ? sm[t - off] : 0;
        __syncthreads();
        if (t >= off) sm[t] += u;
        __syncthreads();
    }
    if (i < N_NODES) g_rowptr[i] = sm[t] - v;   // block-local exclusive
    if (t == 255) g_bsum[b] = sm[255];
}

__global__ __launch_bounds__(256) void k_scan_top() {
    __shared__ int sm[256];
    int t = threadIdx.x;
    int v = (t < SCAN_BLOCKS) ? g_bsum[t] : 0;
    sm[t] = v;
    __syncthreads();
#pragma unroll
    for (int off = 1; off < 256; off <<= 1) {
        int u = (t >= off) ? sm[t - off] : 0;
        __syncthreads();
        if (t >= off) sm[t] += u;
        __syncthreads();
    }
    if (t < SCAN_BLOCKS) g_bsum[t] = sm[t] - v;  // exclusive block offsets
}

// scan finalize + dis = rsqrt(deg+1)
__global__ void k_scan_add() {
    int i = blockIdx.x * blockDim.x + threadIdx.x;
    if (i < N_NODES) {
        int r = g_rowptr[i] + g_bsum[i >> 8];
        g_rowptr[i] = r;
        g_cursor[i] = r;
        g_dis[i] = rsqrtf((float)(g_degi[i] + 1));
    }
    if (i == 0) g_rowptr[N_NODES] = N_EDGES;
}

// ---------------- CSR fill: csrc[slot] = src, cw[slot] = dis[s]*dis[d] ----------------
__global__ void k_fill(const int* __restrict__ src, const int* __restrict__ dst) {
    int e = blockIdx.x * blockDim.x + threadIdx.x;
    if (e >= N_EDGES) return;
    int d = dst[e];
    int s = src[e];
    int pos = atomicAdd(&g_cursor[d], 1);
    g_csrc[pos] = s;
    g_cw[pos] = g_dis[s] * g_dis[d];
}

// ---------------- gather, 64-col fp16 input (layer 1): warp per node ----------------
// lane loads uint (2 halves) -> 32 lanes cover the 128B row. Index prefetch + shfl.
__global__ __launch_bounds__(256) void k_gather64() {
    int t = blockIdx.x * blockDim.x + threadIdx.x;
    int node = t >> 5;
    if (node >= N_NODES) return;
    int lane = t & 31;
    const unsigned* xs = reinterpret_cast<const unsigned*>(g_x16);

    int beg = g_rowptr[node], end = g_rowptr[node + 1];
    int deg = end - beg;

    // prefetch up to 32 edge entries, one per lane
    int eidx = beg + lane;
    int   sl = 0;
    float wl = 0.0f;
    if (eidx < end) { sl = g_csrc[eidx]; wl = g_cw[eidx]; }

    // self loop
    float dd = g_dis[node];
    float w0 = dd * dd;
    unsigned p = xs[(size_t)node * 32 + lane];
    float2 f = __half22float2(*reinterpret_cast<__half2*>(&p));
    float2 acc = make_float2(f.x * w0, f.y * w0);

    int dmin = deg < 32 ? deg : 32;
    for (int j = 0; j < dmin; j++) {
        int   s = __shfl_sync(0xffffffffu, sl, j);
        float w = __shfl_sync(0xffffffffu, wl, j);
        unsigned q = xs[(size_t)s * 32 + lane];
        float2 g2 = __half22float2(*reinterpret_cast<__half2*>(&q));
        acc.x += g2.x * w;
        acc.y += g2.y * w;
    }
    for (int i = beg + 32; i < end; i++) {      // rare tail (deg > 32)
        int   s = g_csrc[i];
        float w = g_cw[i];
        unsigned q = xs[(size_t)s * 32 + lane];
        float2 g2 = __half22float2(*reinterpret_cast<__half2*>(&q));
        acc.x += g2.x * w;
        acc.y += g2.y * w;
    }
    reinterpret_cast<float2*>(g_bufB)[(size_t)node * 32 + lane] = acc;
}

// ---------------- gather, 128-col fp16 hidden (layer 2): warp per node ----------------
// lane loads uint2 (4 halves) -> 32 lanes cover the 256B row.
__global__ __launch_bounds__(256) void k_gather128() {
    int t = blockIdx.x * blockDim.x + threadIdx.x;
    int node = t >> 5;
    if (node >= N_NODES) return;
    int lane = t & 31;
    const uint2* hs = reinterpret_cast<const uint2*>(g_h16);

    int beg = g_rowptr[node], end = g_rowptr[node + 1];
    int deg = end - beg;

    int eidx = beg + lane;
    int   sl = 0;
    float wl = 0.0f;
    if (eidx < end) { sl = g_csrc[eidx]; wl = g_cw[eidx]; }

    float dd = g_dis[node];
    float w0 = dd * dd;
    uint2 p = hs[(size_t)node * 32 + lane];
    float2 fa = __half22float2(*reinterpret_cast<__half2*>(&p.x));
    float2 fb = __half22float2(*reinterpret_cast<__half2*>(&p.y));
    float4 acc = make_float4(fa.x * w0, fa.y * w0, fb.x * w0, fb.y * w0);

    int dmin = deg < 32 ? deg : 32;
    for (int j = 0; j < dmin; j++) {
        int   s = __shfl_sync(0xffffffffu, sl, j);
        float w = __shfl_sync(0xffffffffu, wl, j);
        uint2 q = hs[(size_t)s * 32 + lane];
        float2 ga = __half22float2(*reinterpret_cast<__half2*>(&q.x));
        float2 gb = __half22float2(*reinterpret_cast<__half2*>(&q.y));
        acc.x += ga.x * w; acc.y += ga.y * w;
        acc.z += gb.x * w; acc.w += gb.y * w;
    }
    for (int i = beg + 32; i < end; i++) {
        int   s = g_csrc[i];
        float w = g_cw[i];
        uint2 q = hs[(size_t)s * 32 + lane];
        float2 ga = __half22float2(*reinterpret_cast<__half2*>(&q.x));
        float2 gb = __half22float2(*reinterpret_cast<__half2*>(&q.y));
        acc.x += ga.x * w; acc.y += ga.y * w;
        acc.z += gb.x * w; acc.w += gb.y * w;
    }
    reinterpret_cast<float4*>(g_bufB)[(size_t)node * 32 + lane] = acc;
}

// ---------------- GEMM: relu(bufB[M x K] @ W[K x 128] + bias) ----------------
// H16=true -> write fp16 to g_h16 (layer-1, consumed by gather128); else fp32 to g_bufA.
template <int K, bool H16>
__global__ __launch_bounds__(128) void k_gemm_bias_relu(const float* __restrict__ W,
                                                        const float* __restrict__ bias) {
    constexpr int K4 = K / 4;
    __shared__ float4 xs[64 * K4];
    const int tid = threadIdx.x;
    const int row0 = blockIdx.x * 64;

    for (int idx = tid; idx < 64 * K4; idx += 128) {
        int r = idx / K4;
        int q = idx - r * K4;
        int row = row0 + r;
        float4 v = make_float4(0.f, 0.f, 0.f, 0.f);
        if (row < N_NODES) v = reinterpret_cast<const float4*>(g_bufB)[(size_t)row * K4 + q];
        xs[idx] = v;
    }
    __syncthreads();

    float acc[64];
#pragma unroll
    for (int r = 0; r < 64; r++) acc[r] = 0.0f;

#pragma unroll 1
    for (int k0 = 0; k0 < K; k0 += 8) {
        float w0 = W[(k0 + 0) * HID + tid];
        float w1 = W[(k0 + 1) * HID + tid];
        float w2 = W[(k0 + 2) * HID + tid];
        float w3 = W[(k0 + 3) * HID + tid];
        float w4 = W[(k0 + 4) * HID + tid];
        float w5 = W[(k0 + 5) * HID + tid];
        float w6 = W[(k0 + 6) * HID + tid];
        float w7 = W[(k0 + 7) * HID + tid];
        int q0 = k0 / 4;
#pragma unroll
        for (int r = 0; r < 64; r++) {
            float4 a = xs[r * K4 + q0];
            float4 b = xs[r * K4 + q0 + 1];
            float s = acc[r];
            s += a.x * w0; s += a.y * w1; s += a.z * w2; s += a.w * w3;
            s += b.x * w4; s += b.y * w5; s += b.z * w6; s += b.w * w7;
            acc[r] = s;
        }
    }

    float bv = bias[tid];
#pragma unroll 1
    for (int r = 0; r < 64; r++) {
        int row = row0 + r;
        if (row < N_NODES) {
            float v = fmaxf(acc[r] + bv, 0.0f);
            if (H16) g_h16[(size_t)row * HID + tid] = __float2half_rn(v);
            else     g_bufA[(size_t)row * HID + tid] = v;
        }
    }
}

// ---------------- pooling: pooled[batch[i]] += bufA[i]; cnt[batch[i]] += 1 ----------------
__global__ void k_pool(const int* __restrict__ batch) {
    int t = blockIdx.x * blockDim.x + threadIdx.x;
    int node = t >> 5;
    int lane = t & 31;
    if (node >= N_NODES) return;
    int b = batch[node];
    float4 v = reinterpret_cast<const float4*>(g_bufA)[(size_t)node * 32 + lane];
    float* ap = g_pooled + b * HID + lane * 4;
    red_v4(ap, v.x, v.y, v.z, v.w);
    if (lane == 0) atomicAdd(&g_cnt[b], 1.0f);
}

// ---------------- head: out = relu(mean @ W3 + b3) @ W4 + b4 ----------------
__global__ __launch_bounds__(128) void k_head(const float* __restrict__ W3,
                                              const float* __restrict__ b3,
                                              const float* __restrict__ W4,
                                              const float* __restrict__ b4,
                                              float* __restrict__ out) {
    __shared__ float mean[HID];
    __shared__ float y[HID];
    int b = blockIdx.x;
    int t = threadIdx.x;
    float c = fmaxf(g_cnt[b], 1.0f);
    mean[t] = g_pooled[b * HID + t] / c;
    __syncthreads();

    float acc = b3[t];
#pragma unroll 8
    for (int k = 0; k < HID; k++) acc += mean[k] * W3[k * HID + t];
    y[t] = fmaxf(acc, 0.0f);
    __syncthreads();

    if (t < OUT_DIM) {
        float acc2 = b4[t];
#pragma unroll 8
        for (int k = 0; k < HID; k++) acc2 += y[k] * W4[k * OUT_DIM + t];
        out[b * OUT_DIM + t] = acc2;
    }
}

// ---------------- launch: kernel launches ONLY ----------------
extern "C" void kernel_launch(void* const* d_in, const int* in_sizes, int n_in,
                              void* d_out, int out_size) {
    const float* x     = (const float*)d_in[0];
    const int*   ei    = (const int*)d_in[1];    // int32 (jax x64 disabled)
    const int*   batch = (const int*)d_in[2];
    const float* W1 = (const float*)d_in[3];
    const float* b1 = (const float*)d_in[4];
    const float* W2 = (const float*)d_in[5];
    const float* b2 = (const float*)d_in[6];
    const float* W3 = (const float*)d_in[7];
    const float* b3 = (const float*)d_in[8];
    const float* W4 = (const float*)d_in[9];
    const float* b4 = (const float*)d_in[10];
    float* out = (float*)d_out;

    const int* src = ei;
    const int* dst = ei + N_EDGES;

    // norm + CSR build (+ x fp16 conversion)
    k_zero<<<(N_NODES + 255) / 256, 256>>>();
    k_xcvt<<<(N_NODES * (IN_DIM / 2) + 255) / 256, 256>>>(x);
    k_deg<<<(N_EDGES + 255) / 256, 256>>>(dst);
    k_scan_part<<<SCAN_BLOCKS, 256>>>();
    k_scan_top<<<1, 256>>>();
    k_scan_add<<<(N_NODES + 255) / 256, 256>>>();
    k_fill<<<(N_EDGES + 255) / 256, 256>>>(src, dst);

    // layer 1: aggregate x16 (64 cols) -> bufB, then GEMM -> h16 (fp16)
    k_gather64<<<(N_NODES * 32 + 255) / 256, 256>>>();
    k_gemm_bias_relu<IN_DIM, true><<<(N_NODES + 63) / 64, 128>>>(W1, b1);

    // layer 2: aggregate h16 (128 cols) -> bufB, then GEMM -> bufA (fp32)
    k_gather128<<<(N_NODES * 32 + 255) / 256, 256>>>();
    k_gemm_bias_relu<HID, false><<<(N_NODES + 63) / 64, 128>>>(W2, b2);

    // pool + head
    k_pool<<<(N_NODES * 32 + 255) / 256, 256>>>(batch);
    k_head<<<NB, 128>>>(W3, b3, W4, b4, out);
}

// round 12
// speedup vs baseline: 1.8523x; 1.8523x over previous
#include <cuda_runtime.h>
#include <cuda_fp16.h>
#include <math.h>

#define N_NODES 50000
#define N_EDGES 800000
#define NB      64
#define IN_DIM  64
#define HID     128
#define OUT_DIM 64
#define SCAN_BLOCKS 200   // 200*256 = 51200 >= N_NODES

// ---------------- scratch (device globals: no allocs allowed) ----------------
__device__ __align__(16) int    g_degi[N_NODES];
__device__ __align__(16) float  g_dis[N_NODES];
__device__ __align__(16) int    g_rowptr[N_NODES + 1];
__device__ __align__(16) int    g_cursor[N_NODES];
__device__ __align__(16) int    g_csrc[N_EDGES];
__device__ __align__(16) float  g_cw[N_EDGES];
__device__ __align__(16) int    g_bsum[256];
__device__ __align__(16) __half g_x16[(size_t)N_NODES * IN_DIM];   // fp16 x
__device__ __align__(16) __half g_h16[(size_t)N_NODES * HID];      // fp16 layer-1 output
__device__ __align__(16) __half g_agg16[(size_t)N_NODES * HID];    // fp16 aggregated (GEMM A input)
__device__ __align__(16) __half g_w16a[IN_DIM * HID];              // fp16 W1
__device__ __align__(16) __half g_w16b[HID * HID];                 // fp16 W2
__device__ __align__(16) float  g_bufA[(size_t)N_NODES * HID];     // layer-2 GEMM out (fp32)
__device__ __align__(16) float  g_pooled[NB * HID];
__device__ __align__(16) float  g_cnt[NB];

__device__ __forceinline__ void red_v4(float* ap, float a, float b, float c, float d) {
    asm volatile("red.global.add.v4.f32 [%0], {%1,%2,%3,%4};"
                 :: "l"(ap), "f"(a), "f"(b), "f"(c), "f"(d) : "memory");
}

// ---------------- zero: degi=0, pooled=0, cnt=0 ----------------
__global__ void k_zero() {
    int i = blockIdx.x * blockDim.x + threadIdx.x;
    if (i < N_NODES) g_degi[i] = 0;
    if (i < NB * HID) g_pooled[i] = 0.0f;
    if (i < NB) g_cnt[i] = 0.0f;
}

// ---------------- x -> fp16 ----------------
__global__ void k_xcvt(const float* __restrict__ x) {
    int t = blockIdx.x * blockDim.x + threadIdx.x;
    if (t >= N_NODES * (IN_DIM / 2)) return;
    float2 v = reinterpret_cast<const float2*>(x)[t];
    reinterpret_cast<__half2*>(g_x16)[t] = __floats2half2_rn(v.x, v.y);
}

// ---------------- W1, W2 -> fp16 ----------------
__global__ void k_wcvt(const float* __restrict__ W1, const float* __restrict__ W2) {
    int t = blockIdx.x * blockDim.x + threadIdx.x;
    if (t < IN_DIM * HID) g_w16a[t] = __float2half_rn(W1[t]);
    if (t < HID * HID)    g_w16b[t] = __float2half_rn(W2[t]);
}

// ---------------- degree counts over dst ----------------
__global__ void k_deg(const int* __restrict__ dst) {
    int e = blockIdx.x * blockDim.x + threadIdx.x;
    if (e < N_EDGES) atomicAdd(&g_degi[dst[e]], 1);
}

// ---------------- 2-level exclusive scan of degi -> rowptr ----------------
__global__ __launch_bounds__(256) void k_scan_part() {
    __shared__ int sm[256];
    int b = blockIdx.x, t = threadIdx.x;
    int i = b * 256 + t;
    int v = (i < N_NODES) ? g_degi[i] : 0;
    sm[t] = v;
    __syncthreads();
#pragma unroll
    for (int off = 1; off < 256; off <<= 1) {
        int u = (t >= off) ? sm[t - off] : 0;
        __syncthreads();
        if (t >= off) sm[t] += u;
        __syncthreads();
    }
    if (i < N_NODES) g_rowptr[i] = sm[t] - v;
    if (t == 255) g_bsum[b] = sm[255];
}

__global__ __launch_bounds__(256) void k_scan_top() {
    __shared__ int sm[256];
    int t = threadIdx.x;
    int v = (t < SCAN_BLOCKS) ? g_bsum[t] : 0;
    sm[t] = v;
    __syncthreads();
#pragma unroll
    for (int off = 1; off < 256; off <<= 1) {
        int u = (t >= off) ? sm[t - off] : 0;
        __syncthreads();
        if (t >= off) sm[t] += u;
        __syncthreads();
    }
    if (t < SCAN_BLOCKS) g_bsum[t] = sm[t] - v;
}

__global__ void k_scan_add() {
    int i = blockIdx.x * blockDim.x + threadIdx.x;
    if (i < N_NODES) {
        int r = g_rowptr[i] + g_bsum[i >> 8];
        g_rowptr[i] = r;
        g_cursor[i] = r;
        g_dis[i] = rsqrtf((float)(g_degi[i] + 1));
    }
    if (i == 0) g_rowptr[N_NODES] = N_EDGES;
}

// ---------------- CSR fill ----------------
__global__ void k_fill(const int* __restrict__ src, const int* __restrict__ dst) {
    int e = blockIdx.x * blockDim.x + threadIdx.x;
    if (e >= N_EDGES) return;
    int d = dst[e];
    int s = src[e];
    int pos = atomicAdd(&g_cursor[d], 1);
    g_csrc[pos] = s;
    g_cw[pos] = g_dis[s] * g_dis[d];
}

// ---------------- gather, 64-col fp16 (layer 1): warp per node ----------------
__global__ __launch_bounds__(256) void k_gather64() {
    int t = blockIdx.x * blockDim.x + threadIdx.x;
    int node = t >> 5;
    if (node >= N_NODES) return;
    int lane = t & 31;
    const unsigned* xs = reinterpret_cast<const unsigned*>(g_x16);

    int beg = g_rowptr[node], end = g_rowptr[node + 1];
    float dd = g_dis[node];
    float w0 = dd * dd;
    unsigned p = xs[(size_t)node * 32 + lane];
    float2 f = __half22float2(*reinterpret_cast<__half2*>(&p));
    float2 acc = make_float2(f.x * w0, f.y * w0);

    int i = beg;
    for (; i + 2 <= end; i += 2) {
        int s0 = g_csrc[i], s1 = g_csrc[i + 1];
        float wa = g_cw[i], wb = g_cw[i + 1];
        unsigned q0 = xs[(size_t)s0 * 32 + lane];
        unsigned q1 = xs[(size_t)s1 * 32 + lane];
        float2 a0 = __half22float2(*reinterpret_cast<__half2*>(&q0));
        float2 a1 = __half22float2(*reinterpret_cast<__half2*>(&q1));
        acc.x += a0.x * wa + a1.x * wb;
        acc.y += a0.y * wa + a1.y * wb;
    }
    if (i < end) {
        int s = g_csrc[i];
        float w = g_cw[i];
        unsigned q = xs[(size_t)s * 32 + lane];
        float2 a = __half22float2(*reinterpret_cast<__half2*>(&q));
        acc.x += a.x * w;
        acc.y += a.y * w;
    }
    reinterpret_cast<__half2*>(g_agg16)[(size_t)node * 32 + lane] = __floats2half2_rn(acc.x, acc.y);
}

// ---------------- gather, 128-col fp16 (layer 2): warp per node ----------------
__global__ __launch_bounds__(256) void k_gather128() {
    int t = blockIdx.x * blockDim.x + threadIdx.x;
    int node = t >> 5;
    if (node >= N_NODES) return;
    int lane = t & 31;
    const uint2* hs = reinterpret_cast<const uint2*>(g_h16);

    int beg = g_rowptr[node], end = g_rowptr[node + 1];
    float dd = g_dis[node];
    float w0 = dd * dd;
    uint2 p = hs[(size_t)node * 32 + lane];
    float2 fa = __half22float2(*reinterpret_cast<__half2*>(&p.x));
    float2 fb = __half22float2(*reinterpret_cast<__half2*>(&p.y));
    float4 acc = make_float4(fa.x * w0, fa.y * w0, fb.x * w0, fb.y * w0);

    int i = beg;
    for (; i + 2 <= end; i += 2) {
        int s0 = g_csrc[i], s1 = g_csrc[i + 1];
        float wa = g_cw[i], wb = g_cw[i + 1];
        uint2 q0 = hs[(size_t)s0 * 32 + lane];
        uint2 q1 = hs[(size_t)s1 * 32 + lane];
        float2 a0 = __half22float2(*reinterpret_cast<__half2*>(&q0.x));
        float2 b0 = __half22float2(*reinterpret_cast<__half2*>(&q0.y));
        float2 a1 = __half22float2(*reinterpret_cast<__half2*>(&q1.x));
        float2 b1 = __half22float2(*reinterpret_cast<__half2*>(&q1.y));
        acc.x += a0.x * wa + a1.x * wb;
        acc.y += a0.y * wa + a1.y * wb;
        acc.z += b0.x * wa + b1.x * wb;
        acc.w += b0.y * wa + b1.y * wb;
    }
    if (i < end) {
        int s = g_csrc[i];
        float w = g_cw[i];
        uint2 q = hs[(size_t)s * 32 + lane];
        float2 a = __half22float2(*reinterpret_cast<__half2*>(&q.x));
        float2 b = __half22float2(*reinterpret_cast<__half2*>(&q.y));
        acc.x += a.x * w; acc.y += a.y * w;
        acc.z += b.x * w; acc.w += b.y * w;
    }
    __half2 h0 = __floats2half2_rn(acc.x, acc.y);
    __half2 h1 = __floats2half2_rn(acc.z, acc.w);
    unsigned u0 = *reinterpret_cast<unsigned*>(&h0);
    unsigned u1 = *reinterpret_cast<unsigned*>(&h1);
    reinterpret_cast<uint2*>(g_agg16)[(size_t)node * 32 + lane] = make_uint2(u0, u1);
}

// ---------------- tensor-core GEMM: out = relu(agg16[M x K] @ W16[K x 128] + bias) ----------------
// W16 selected INSIDE the kernel (device-symbol args from host are invalid!).
// block = 128 threads (4 warps), 64 rows/block; W in two 64-col halves (static smem < 48KB).
template <int K, bool H16OUT>
__global__ __launch_bounds__(128) void k_gemm_mma(const float* __restrict__ bias) {
    const __half* W16 = H16OUT ? g_w16a : g_w16b;   // layer1 -> W1, layer2 -> W2
    constexpr int LDA = K + 8;      // halves; +16B pad vs LDSM conflicts
    constexpr int LDW = 64 + 8;     // 72 halves per W row (one 64-col half)
    __shared__ __half As[64 * LDA];
    __shared__ __half Ws[K * LDW];

    const int tid  = threadIdx.x;
    const int lane = tid & 31;
    const int w    = tid >> 5;
    const int row0 = blockIdx.x * 64;

    // load A tile (64 x K fp16), zero-fill OOB rows
    {
        constexpr int RV = K / 8;               // uint4 per row
        for (int idx = tid; idx < 64 * RV; idx += 128) {
            int r = idx / RV, c = idx - r * RV;
            uint4 v = make_uint4(0u, 0u, 0u, 0u);
            int row = row0 + r;
            if (row < N_NODES)
                v = reinterpret_cast<const uint4*>(g_agg16)[(size_t)row * RV + c];
            *reinterpret_cast<uint4*>(&As[r * LDA + c * 8]) = v;
        }
    }

    float acc[16][4];
#pragma unroll
    for (int nt = 0; nt < 16; nt++)
#pragma unroll
        for (int j = 0; j < 4; j++) acc[nt][j] = 0.0f;

#pragma unroll
    for (int h = 0; h < 2; h++) {
        __syncthreads();
        // load W half-tile (K x 64 fp16): global cols [h*64, h*64+64)
        {
            constexpr int RV = 64 / 8;          // 8 uint4 per row-half
            for (int idx = tid; idx < K * RV; idx += 128) {
                int r = idx / RV, c = idx - r * RV;
                uint4 v = reinterpret_cast<const uint4*>(W16 + (size_t)r * HID + h * 64)[c];
                *reinterpret_cast<uint4*>(&Ws[r * LDW + c * 8]) = v;
            }
        }
        __syncthreads();

#pragma unroll
        for (int ks = 0; ks < K / 16; ks++) {
            // A fragment via ldmatrix.x4
            unsigned a0, a1, a2, a3;
            {
                int tile = lane >> 3, lrow = lane & 7;
                int arow = w * 16 + (tile & 1) * 8 + lrow;
                int acol = ks * 16 + (tile >> 1) * 8;
                unsigned addr = (unsigned)__cvta_generic_to_shared(&As[arow * LDA + acol]);
                asm volatile("ldmatrix.sync.aligned.m8n8.x4.shared.b16 {%0,%1,%2,%3}, [%4];"
                             : "=r"(a0), "=r"(a1), "=r"(a2), "=r"(a3) : "r"(addr));
            }
#pragma unroll
            for (int nt = 0; nt < 8; nt++) {
                unsigned b0, b1;
                {
                    int l = lane & 15;
                    int krow = ks * 16 + l;
                    unsigned addr = (unsigned)__cvta_generic_to_shared(&Ws[krow * LDW + nt * 8]);
                    asm volatile("ldmatrix.sync.aligned.m8n8.x2.trans.shared.b16 {%0,%1}, [%2];"
                                 : "=r"(b0), "=r"(b1) : "r"(addr));
                }
                float* a4 = acc[h * 8 + nt];
                asm volatile("mma.sync.aligned.m16n8k16.row.col.f32.f16.f16.f32 "
                             "{%0,%1,%2,%3}, {%4,%5,%6,%7}, {%8,%9}, {%0,%1,%2,%3};"
                             : "+f"(a4[0]), "+f"(a4[1]), "+f"(a4[2]), "+f"(a4[3])
                             : "r"(a0), "r"(a1), "r"(a2), "r"(a3), "r"(b0), "r"(b1));
            }
        }
    }

    // epilogue: bias + relu, store
    int g  = lane >> 2;
    int tq = lane & 3;
    int ra = row0 + w * 16 + g;
    int rb = ra + 8;
#pragma unroll
    for (int nt = 0; nt < 16; nt++) {
        int col = nt * 8 + tq * 2;
        float bv0 = bias[col], bv1 = bias[col + 1];
        float v0 = fmaxf(acc[nt][0] + bv0, 0.0f);
        float v1 = fmaxf(acc[nt][1] + bv1, 0.0f);
        float v2 = fmaxf(acc[nt][2] + bv0, 0.0f);
        float v3 = fmaxf(acc[nt][3] + bv1, 0.0f);
        if (H16OUT) {
            if (ra < N_NODES)
                *reinterpret_cast<__half2*>(&g_h16[(size_t)ra * HID + col]) = __floats2half2_rn(v0, v1);
            if (rb < N_NODES)
                *reinterpret_cast<__half2*>(&g_h16[(size_t)rb * HID + col]) = __floats2half2_rn(v2, v3);
        } else {
            if (ra < N_NODES)
                *reinterpret_cast<float2*>(&g_bufA[(size_t)ra * HID + col]) = make_float2(v0, v1);
            if (rb < N_NODES)
                *reinterpret_cast<float2*>(&g_bufA[(size_t)rb * HID + col]) = make_float2(v2, v3);
        }
    }
}

// ---------------- pooling ----------------
__global__ void k_pool(const int* __restrict__ batch) {
    int t = blockIdx.x * blockDim.x + threadIdx.x;
    int node = t >> 5;
    int lane = t & 31;
    if (node >= N_NODES) return;
    int b = batch[node];
    float4 v = reinterpret_cast<const float4*>(g_bufA)[(size_t)node * 32 + lane];
    float* ap = g_pooled + b * HID + lane * 4;
    red_v4(ap, v.x, v.y, v.z, v.w);
    if (lane == 0) atomicAdd(&g_cnt[b], 1.0f);
}

// ---------------- head ----------------
__global__ __launch_bounds__(128) void k_head(const float* __restrict__ W3,
                                              const float* __restrict__ b3,
                                              const float* __restrict__ W4,
                                              const float* __restrict__ b4,
                                              float* __restrict__ out) {
    __shared__ float mean[HID];
    __shared__ float y[HID];
    int b = blockIdx.x;
    int t = threadIdx.x;
    float c = fmaxf(g_cnt[b], 1.0f);
    mean[t] = g_pooled[b * HID + t] / c;
    __syncthreads();

    float acc = b3[t];
#pragma unroll 8
    for (int k = 0; k < HID; k++) acc += mean[k] * W3[k * HID + t];
    y[t] = fmaxf(acc, 0.0f);
    __syncthreads();

    if (t < OUT_DIM) {
        float acc2 = b4[t];
#pragma unroll 8
        for (int k = 0; k < HID; k++) acc2 += y[k] * W4[k * OUT_DIM + t];
        out[b * OUT_DIM + t] = acc2;
    }
}

// ---------------- launch ----------------
extern "C" void kernel_launch(void* const* d_in, const int* in_sizes, int n_in,
                              void* d_out, int out_size) {
    const float* x     = (const float*)d_in[0];
    const int*   ei    = (const int*)d_in[1];
    const int*   batch = (const int*)d_in[2];
    const float* W1 = (const float*)d_in[3];
    const float* b1 = (const float*)d_in[4];
    const float* W2 = (const float*)d_in[5];
    const float* b2 = (const float*)d_in[6];
    const float* W3 = (const float*)d_in[7];
    const float* b3 = (const float*)d_in[8];
    const float* W4 = (const float*)d_in[9];
    const float* b4 = (const float*)d_in[10];
    float* out = (float*)d_out;

    const int* src = ei;
    const int* dst = ei + N_EDGES;

    // prelude: norm + CSR build + fp16 conversions
    k_zero<<<(N_NODES + 255) / 256, 256>>>();
    k_xcvt<<<(N_NODES * (IN_DIM / 2) + 255) / 256, 256>>>(x);
    k_wcvt<<<(HID * HID + 255) / 256, 256>>>(W1, W2);
    k_deg<<<(N_EDGES + 255) / 256, 256>>>(dst);
    k_scan_part<<<SCAN_BLOCKS, 256>>>();
    k_scan_top<<<1, 256>>>();
    k_scan_add<<<(N_NODES + 255) / 256, 256>>>();
    k_fill<<<(N_EDGES + 255) / 256, 256>>>(src, dst);

    // layer 1: gather x16 -> agg16, tensor GEMM (W1) -> h16 (fp16)
    k_gather64<<<(N_NODES * 32 + 255) / 256, 256>>>();
    k_gemm_mma<IN_DIM, true><<<(N_NODES + 63) / 64, 128>>>(b1);

    // layer 2: gather h16 -> agg16, tensor GEMM (W2) -> bufA (fp32)
    k_gather128<<<(N_NODES * 32 + 255) / 256, 256>>>();
    k_gemm_mma<HID, false><<<(N_NODES + 63) / 64, 128>>>(b2);

    // pool + head
    k_pool<<<(N_NODES * 32 + 255) / 256, 256>>>(batch);
    k_head<<<NB, 128>>>(W3, b3, W4, b4, out);
}

// round 13
// speedup vs baseline: 1.8944x; 1.0228x over previous
#include <cuda_runtime.h>
#include <cuda_fp16.h>
#include <math.h>

#define N_NODES 50000
#define N_EDGES 800000
#define NB      64
#define IN_DIM  64
#define HID     128
#define OUT_DIM 64
#define SCAN_BLOCKS 200   // 200*256 = 51200 >= N_NODES

// ---------------- scratch (device globals: no allocs allowed) ----------------
__device__ __align__(16) int    g_degi[N_NODES];
__device__ __align__(16) float  g_dis[N_NODES];
__device__ __align__(16) int    g_rowptr[N_NODES + 1];
__device__ __align__(16) int    g_cursor[N_NODES];
__device__ __align__(16) int    g_csrc[N_EDGES];
__device__ __align__(16) float  g_cw[N_EDGES];
__device__ __align__(16) int    g_bsum[256];
__device__ __align__(16) __half g_x16[(size_t)N_NODES * IN_DIM];   // fp16 x
__device__ __align__(16) __half g_h16[(size_t)N_NODES * HID];      // fp16 layer-1 output
__device__ __align__(16) __half g_agg16[(size_t)N_NODES * HID];    // fp16 aggregated (GEMM A input)
__device__ __align__(16) __half g_w16a[IN_DIM * HID];              // fp16 W1
__device__ __align__(16) __half g_w16b[HID * HID];                 // fp16 W2
__device__ __align__(16) float  g_bufA[(size_t)N_NODES * HID];     // layer-2 GEMM out (fp32)
__device__ __align__(16) float  g_pooled[NB * HID];
__device__ __align__(16) float  g_cnt[NB];

__device__ __forceinline__ void red_v4(float* ap, float a, float b, float c, float d) {
    asm volatile("red.global.add.v4.f32 [%0], {%1,%2,%3,%4};"
                 :: "l"(ap), "f"(a), "f"(b), "f"(c), "f"(d) : "memory");
}

// ---------------- fused prelude: degi=0, pooled=0, cnt=0, x->fp16, W->fp16 ----------------
__global__ void k_prelude(const float* __restrict__ x,
                          const float* __restrict__ W1, const float* __restrict__ W2) {
    int t = blockIdx.x * blockDim.x + threadIdx.x;
    if (t < N_NODES * (IN_DIM / 2)) {
        float2 v = reinterpret_cast<const float2*>(x)[t];
        reinterpret_cast<__half2*>(g_x16)[t] = __floats2half2_rn(v.x, v.y);
    }
    if (t < N_NODES) g_degi[t] = 0;
    if (t < NB * HID) g_pooled[t] = 0.0f;
    if (t < NB) g_cnt[t] = 0.0f;
    if (t < IN_DIM * HID) g_w16a[t] = __float2half_rn(W1[t]);
    if (t < HID * HID)    g_w16b[t] = __float2half_rn(W2[t]);
}

// ---------------- degree counts over dst: int4, 4 edges/thread ----------------
__global__ void k_deg(const int* __restrict__ dst) {
    int t = blockIdx.x * blockDim.x + threadIdx.x;
    if (t >= N_EDGES / 4) return;
    int4 d4 = reinterpret_cast<const int4*>(dst)[t];
    atomicAdd(&g_degi[d4.x], 1);
    atomicAdd(&g_degi[d4.y], 1);
    atomicAdd(&g_degi[d4.z], 1);
    atomicAdd(&g_degi[d4.w], 1);
}

// ---------------- 2-level exclusive scan of degi -> rowptr ----------------
__global__ __launch_bounds__(256) void k_scan_part() {
    __shared__ int sm[256];
    int b = blockIdx.x, t = threadIdx.x;
    int i = b * 256 + t;
    int v = (i < N_NODES) ? g_degi[i] : 0;
    sm[t] = v;
    __syncthreads();
#pragma unroll
    for (int off = 1; off < 256; off <<= 1) {
        int u = (t >= off) ? sm[t - off] : 0;
        __syncthreads();
        if (t >= off) sm[t] += u;
        __syncthreads();
    }
    if (i < N_NODES) g_rowptr[i] = sm[t] - v;
    if (t == 255) g_bsum[b] = sm[255];
}

__global__ __launch_bounds__(256) void k_scan_top() {
    __shared__ int sm[256];
    int t = threadIdx.x;
    int v = (t < SCAN_BLOCKS) ? g_bsum[t] : 0;
    sm[t] = v;
    __syncthreads();
#pragma unroll
    for (int off = 1; off < 256; off <<= 1) {
        int u = (t >= off) ? sm[t - off] : 0;
        __syncthreads();
        if (t >= off) sm[t] += u;
        __syncthreads();
    }
    if (t < SCAN_BLOCKS) g_bsum[t] = sm[t] - v;
}

__global__ void k_scan_add() {
    int i = blockIdx.x * blockDim.x + threadIdx.x;
    if (i < N_NODES) {
        int r = g_rowptr[i] + g_bsum[i >> 8];
        g_rowptr[i] = r;
        g_cursor[i] = r;
        g_dis[i] = rsqrtf((float)(g_degi[i] + 1));
    }
    if (i == 0) g_rowptr[N_NODES] = N_EDGES;
}

// ---------------- CSR fill ----------------
__global__ void k_fill(const int* __restrict__ src, const int* __restrict__ dst) {
    int e = blockIdx.x * blockDim.x + threadIdx.x;
    if (e >= N_EDGES) return;
    int d = dst[e];
    int s = src[e];
    int pos = atomicAdd(&g_cursor[d], 1);
    g_csrc[pos] = s;
    g_cw[pos] = g_dis[s] * g_dis[d];
}

// ---------------- gather, 64-col fp16 (layer 1): warp per node, 4-edge unroll ----------------
__global__ __launch_bounds__(256) void k_gather64() {
    int t = blockIdx.x * blockDim.x + threadIdx.x;
    int node = t >> 5;
    if (node >= N_NODES) return;
    int lane = t & 31;
    const unsigned* xs = reinterpret_cast<const unsigned*>(g_x16);

    int beg = g_rowptr[node], end = g_rowptr[node + 1];
    float dd = g_dis[node];
    float w0 = dd * dd;
    unsigned p = xs[(size_t)node * 32 + lane];
    float2 f = __half22float2(*reinterpret_cast<__half2*>(&p));
    float2 acc = make_float2(f.x * w0, f.y * w0);

    int i = beg;
    for (; i + 4 <= end; i += 4) {
        int s0 = g_csrc[i],     s1 = g_csrc[i + 1];
        int s2 = g_csrc[i + 2], s3 = g_csrc[i + 3];
        float wa = g_cw[i],     wb = g_cw[i + 1];
        float wc = g_cw[i + 2], wd = g_cw[i + 3];
        unsigned q0 = xs[(size_t)s0 * 32 + lane];
        unsigned q1 = xs[(size_t)s1 * 32 + lane];
        unsigned q2 = xs[(size_t)s2 * 32 + lane];
        unsigned q3 = xs[(size_t)s3 * 32 + lane];
        float2 a0 = __half22float2(*reinterpret_cast<__half2*>(&q0));
        float2 a1 = __half22float2(*reinterpret_cast<__half2*>(&q1));
        float2 a2 = __half22float2(*reinterpret_cast<__half2*>(&q2));
        float2 a3 = __half22float2(*reinterpret_cast<__half2*>(&q3));
        acc.x += a0.x * wa + a1.x * wb + a2.x * wc + a3.x * wd;
        acc.y += a0.y * wa + a1.y * wb + a2.y * wc + a3.y * wd;
    }
    for (; i < end; i++) {
        int s = g_csrc[i];
        float w = g_cw[i];
        unsigned q = xs[(size_t)s * 32 + lane];
        float2 a = __half22float2(*reinterpret_cast<__half2*>(&q));
        acc.x += a.x * w;
        acc.y += a.y * w;
    }
    reinterpret_cast<__half2*>(g_agg16)[(size_t)node * 32 + lane] = __floats2half2_rn(acc.x, acc.y);
}

// ---------------- gather, 128-col fp16 (layer 2): warp per node, 4-edge unroll ----------------
__global__ __launch_bounds__(256) void k_gather128() {
    int t = blockIdx.x * blockDim.x + threadIdx.x;
    int node = t >> 5;
    if (node >= N_NODES) return;
    int lane = t & 31;
    const uint2* hs = reinterpret_cast<const uint2*>(g_h16);

    int beg = g_rowptr[node], end = g_rowptr[node + 1];
    float dd = g_dis[node];
    float w0 = dd * dd;
    uint2 p = hs[(size_t)node * 32 + lane];
    float2 fa = __half22float2(*reinterpret_cast<__half2*>(&p.x));
    float2 fb = __half22float2(*reinterpret_cast<__half2*>(&p.y));
    float4 acc = make_float4(fa.x * w0, fa.y * w0, fb.x * w0, fb.y * w0);

    int i = beg;
    for (; i + 4 <= end; i += 4) {
        int s0 = g_csrc[i],     s1 = g_csrc[i + 1];
        int s2 = g_csrc[i + 2], s3 = g_csrc[i + 3];
        float wa = g_cw[i],     wb = g_cw[i + 1];
        float wc = g_cw[i + 2], wd = g_cw[i + 3];
        uint2 q0 = hs[(size_t)s0 * 32 + lane];
        uint2 q1 = hs[(size_t)s1 * 32 + lane];
        uint2 q2 = hs[(size_t)s2 * 32 + lane];
        uint2 q3 = hs[(size_t)s3 * 32 + lane];
        float2 a0 = __half22float2(*reinterpret_cast<__half2*>(&q0.x));
        float2 b0 = __half22float2(*reinterpret_cast<__half2*>(&q0.y));
        float2 a1 = __half22float2(*reinterpret_cast<__half2*>(&q1.x));
        float2 b1 = __half22float2(*reinterpret_cast<__half2*>(&q1.y));
        float2 a2 = __half22float2(*reinterpret_cast<__half2*>(&q2.x));
        float2 b2 = __half22float2(*reinterpret_cast<__half2*>(&q2.y));
        float2 a3 = __half22float2(*reinterpret_cast<__half2*>(&q3.x));
        float2 b3 = __half22float2(*reinterpret_cast<__half2*>(&q3.y));
        acc.x += a0.x * wa + a1.x * wb + a2.x * wc + a3.x * wd;
        acc.y += a0.y * wa + a1.y * wb + a2.y * wc + a3.y * wd;
        acc.z += b0.x * wa + b1.x * wb + b2.x * wc + b3.x * wd;
        acc.w += b0.y * wa + b1.y * wb + b2.y * wc + b3.y * wd;
    }
    for (; i < end; i++) {
        int s = g_csrc[i];
        float w = g_cw[i];
        uint2 q = hs[(size_t)s * 32 + lane];
        float2 a = __half22float2(*reinterpret_cast<__half2*>(&q.x));
        float2 b = __half22float2(*reinterpret_cast<__half2*>(&q.y));
        acc.x += a.x * w; acc.y += a.y * w;
        acc.z += b.x * w; acc.w += b.y * w;
    }
    __half2 h0 = __floats2half2_rn(acc.x, acc.y);
    __half2 h1 = __floats2half2_rn(acc.z, acc.w);
    unsigned u0 = *reinterpret_cast<unsigned*>(&h0);
    unsigned u1 = *reinterpret_cast<unsigned*>(&h1);
    reinterpret_cast<uint2*>(g_agg16)[(size_t)node * 32 + lane] = make_uint2(u0, u1);
}

// ---------------- tensor-core GEMM: out = relu(agg16[M x K] @ W16[K x 128] + bias) ----------------
template <int K, bool H16OUT>
__global__ __launch_bounds__(128) void k_gemm_mma(const float* __restrict__ bias) {
    const __half* W16 = H16OUT ? g_w16a : g_w16b;   // layer1 -> W1, layer2 -> W2
    constexpr int LDA = K + 8;
    constexpr int LDW = 64 + 8;
    __shared__ __half As[64 * LDA];
    __shared__ __half Ws[K * LDW];

    const int tid  = threadIdx.x;
    const int lane = tid & 31;
    const int w    = tid >> 5;
    const int row0 = blockIdx.x * 64;

    {
        constexpr int RV = K / 8;
        for (int idx = tid; idx < 64 * RV; idx += 128) {
            int r = idx / RV, c = idx - r * RV;
            uint4 v = make_uint4(0u, 0u, 0u, 0u);
            int row = row0 + r;
            if (row < N_NODES)
                v = reinterpret_cast<const uint4*>(g_agg16)[(size_t)row * RV + c];
            *reinterpret_cast<uint4*>(&As[r * LDA + c * 8]) = v;
        }
    }

    float acc[16][4];
#pragma unroll
    for (int nt = 0; nt < 16; nt++)
#pragma unroll
        for (int j = 0; j < 4; j++) acc[nt][j] = 0.0f;

#pragma unroll
    for (int h = 0; h < 2; h++) {
        __syncthreads();
        {
            constexpr int RV = 64 / 8;
            for (int idx = tid; idx < K * RV; idx += 128) {
                int r = idx / RV, c = idx - r * RV;
                uint4 v = reinterpret_cast<const uint4*>(W16 + (size_t)r * HID + h * 64)[c];
                *reinterpret_cast<uint4*>(&Ws[r * LDW + c * 8]) = v;
            }
        }
        __syncthreads();

#pragma unroll
        for (int ks = 0; ks < K / 16; ks++) {
            unsigned a0, a1, a2, a3;
            {
                int tile = lane >> 3, lrow = lane & 7;
                int arow = w * 16 + (tile & 1) * 8 + lrow;
                int acol = ks * 16 + (tile >> 1) * 8;
                unsigned addr = (unsigned)__cvta_generic_to_shared(&As[arow * LDA + acol]);
                asm volatile("ldmatrix.sync.aligned.m8n8.x4.shared.b16 {%0,%1,%2,%3}, [%4];"
                             : "=r"(a0), "=r"(a1), "=r"(a2), "=r"(a3) : "r"(addr));
            }
#pragma unroll
            for (int nt = 0; nt < 8; nt++) {
                unsigned b0, b1;
                {
                    int l = lane & 15;
                    int krow = ks * 16 + l;
                    unsigned addr = (unsigned)__cvta_generic_to_shared(&Ws[krow * LDW + nt * 8]);
                    asm volatile("ldmatrix.sync.aligned.m8n8.x2.trans.shared.b16 {%0,%1}, [%2];"
                                 : "=r"(b0), "=r"(b1) : "r"(addr));
                }
                float* a4 = acc[h * 8 + nt];
                asm volatile("mma.sync.aligned.m16n8k16.row.col.f32.f16.f16.f32 "
                             "{%0,%1,%2,%3}, {%4,%5,%6,%7}, {%8,%9}, {%0,%1,%2,%3};"
                             : "+f"(a4[0]), "+f"(a4[1]), "+f"(a4[2]), "+f"(a4[3])
                             : "r"(a0), "r"(a1), "r"(a2), "r"(a3), "r"(b0), "r"(b1));
            }
        }
    }

    int g  = lane >> 2;
    int tq = lane & 3;
    int ra = row0 + w * 16 + g;
    int rb = ra + 8;
#pragma unroll
    for (int nt = 0; nt < 16; nt++) {
        int col = nt * 8 + tq * 2;
        float bv0 = bias[col], bv1 = bias[col + 1];
        float v0 = fmaxf(acc[nt][0] + bv0, 0.0f);
        float v1 = fmaxf(acc[nt][1] + bv1, 0.0f);
        float v2 = fmaxf(acc[nt][2] + bv0, 0.0f);
        float v3 = fmaxf(acc[nt][3] + bv1, 0.0f);
        if (H16OUT) {
            if (ra < N_NODES)
                *reinterpret_cast<__half2*>(&g_h16[(size_t)ra * HID + col]) = __floats2half2_rn(v0, v1);
            if (rb < N_NODES)
                *reinterpret_cast<__half2*>(&g_h16[(size_t)rb * HID + col]) = __floats2half2_rn(v2, v3);
        } else {
            if (ra < N_NODES)
                *reinterpret_cast<float2*>(&g_bufA[(size_t)ra * HID + col]) = make_float2(v0, v1);
            if (rb < N_NODES)
                *reinterpret_cast<float2*>(&g_bufA[(size_t)rb * HID + col]) = make_float2(v2, v3);
        }
    }
}

// ---------------- pooling ----------------
__global__ void k_pool(const int* __restrict__ batch) {
    int t = blockIdx.x * blockDim.x + threadIdx.x;
    int node = t >> 5;
    int lane = t & 31;
    if (node >= N_NODES) return;
    int b = batch[node];
    float4 v = reinterpret_cast<const float4*>(g_bufA)[(size_t)node * 32 + lane];
    float* ap = g_pooled + b * HID + lane * 4;
    red_v4(ap, v.x, v.y, v.z, v.w);
    if (lane == 0) atomicAdd(&g_cnt[b], 1.0f);
}

// ---------------- head ----------------
__global__ __launch_bounds__(128) void k_head(const float* __restrict__ W3,
                                              const float* __restrict__ b3,
                                              const float* __restrict__ W4,
                                              const float* __restrict__ b4,
                                              float* __restrict__ out) {
    __shared__ float mean[HID];
    __shared__ float y[HID];
    int b = blockIdx.x;
    int t = threadIdx.x;
    float c = fmaxf(g_cnt[b], 1.0f);
    mean[t] = g_pooled[b * HID + t] / c;
    __syncthreads();

    float acc = b3[t];
#pragma unroll 8
    for (int k = 0; k < HID; k++) acc += mean[k] * W3[k * HID + t];
    y[t] = fmaxf(acc, 0.0f);
    __syncthreads();

    if (t < OUT_DIM) {
        float acc2 = b4[t];
#pragma unroll 8
        for (int k = 0; k < HID; k++) acc2 += y[k] * W4[k * OUT_DIM + t];
        out[b * OUT_DIM + t] = acc2;
    }
}

// ---------------- launch ----------------
extern "C" void kernel_launch(void* const* d_in, const int* in_sizes, int n_in,
                              void* d_out, int out_size) {
    const float* x     = (const float*)d_in[0];
    const int*   ei    = (const int*)d_in[1];
    const int*   batch = (const int*)d_in[2];
    const float* W1 = (const float*)d_in[3];
    const float* b1 = (const float*)d_in[4];
    const float* W2 = (const float*)d_in[5];
    const float* b2 = (const float*)d_in[6];
    const float* W3 = (const float*)d_in[7];
    const float* b3 = (const float*)d_in[8];
    const float* W4 = (const float*)d_in[9];
    const float* b4 = (const float*)d_in[10];
    float* out = (float*)d_out;

    const int* src = ei;
    const int* dst = ei + N_EDGES;

    // prelude: fused init/convert, then norm + CSR build
    k_prelude<<<(N_NODES * (IN_DIM / 2) + 255) / 256, 256>>>(x, W1, W2);
    k_deg<<<(N_EDGES / 4 + 255) / 256, 256>>>(dst);
    k_scan_part<<<SCAN_BLOCKS, 256>>>();
    k_scan_top<<<1, 256>>>();
    k_scan_add<<<(N_NODES + 255) / 256, 256>>>();
    k_fill<<<(N_EDGES + 255) / 256, 256>>>(src, dst);

    // layer 1: gather x16 -> agg16, tensor GEMM (W1) -> h16 (fp16)
    k_gather64<<<(N_NODES * 32 + 255) / 256, 256>>>();
    k_gemm_mma<IN_DIM, true><<<(N_NODES + 63) / 64, 128>>>(b1);

    // layer 2: gather h16 -> agg16, tensor GEMM (W2) -> bufA (fp32)
    k_gather128<<<(N_NODES * 32 + 255) / 256, 256>>>();
    k_gemm_mma<HID, false><<<(N_NODES + 63) / 64, 128>>>(b2);

    // pool + head
    k_pool<<<(N_NODES * 32 + 255) / 256, 256>>>(batch);
    k_head<<<NB, 128>>>(W3, b3, W4, b4, out);
}

// round 15
// speedup vs baseline: 2.4799x; 1.3091x over previous
#include <cuda_runtime.h>
#include <cuda_fp16.h>
#include <math.h>

#define N_NODES 50000
#define N_EDGES 800000
#define NB      64
#define IN_DIM  64
#define HID     128
#define OUT_DIM 64
#define SCAN_BLOCKS 196   // 196*256 = 50176 >= N_NODES

// ---------------- scratch (device globals: no allocs allowed) ----------------
__device__ __align__(16) int    g_degi[N_NODES];
__device__ __align__(16) float  g_dis[N_NODES];
__device__ __align__(16) int    g_rowptr[N_NODES + 1];
__device__ __align__(16) int    g_cursor[N_NODES];
__device__ __align__(16) int    g_csrc[N_EDGES];
__device__ __align__(16) float  g_cw[N_EDGES];
__device__ __align__(16) unsigned long long g_state[SCAN_BLOCKS];  // lookback state
__device__ __align__(16) __half g_x16[(size_t)N_NODES * IN_DIM];   // fp16 x
__device__ __align__(16) __half g_h16[(size_t)N_NODES * HID];      // fp16 layer-1 output
__device__ __align__(16) __half g_agg16[(size_t)N_NODES * HID];    // fp16 aggregated (GEMM A input)
__device__ __align__(16) __half g_w16a[IN_DIM * HID];              // fp16 W1
__device__ __align__(16) __half g_w16b[HID * HID];                 // fp16 W2
__device__ __align__(16) float  g_bufA[(size_t)N_NODES * HID];     // layer-2 GEMM out (fp32)
__device__ __align__(16) float  g_pooled[NB * HID];
__device__ __align__(16) float  g_cnt[NB];

// ---------------- fused prelude: zeros + x->fp16 + W->fp16 ----------------
__global__ void k_prelude(const float* __restrict__ x,
                          const float* __restrict__ W1, const float* __restrict__ W2) {
    int t = blockIdx.x * blockDim.x + threadIdx.x;
    if (t < N_NODES * (IN_DIM / 2)) {
        float2 v = reinterpret_cast<const float2*>(x)[t];
        reinterpret_cast<__half2*>(g_x16)[t] = __floats2half2_rn(v.x, v.y);
    }
    if (t < N_NODES) g_degi[t] = 0;
    if (t < NB * HID) g_pooled[t] = 0.0f;
    if (t < NB) g_cnt[t] = 0.0f;
    if (t < SCAN_BLOCKS) g_state[t] = 0ull;
    if (t < IN_DIM * HID) g_w16a[t] = __float2half_rn(W1[t]);
    if (t < HID * HID)    g_w16b[t] = __float2half_rn(W2[t]);
}

// ---------------- degree counts over dst: int4, 4 edges/thread ----------------
__global__ void k_deg(const int* __restrict__ dst) {
    int t = blockIdx.x * blockDim.x + threadIdx.x;
    if (t >= N_EDGES / 4) return;
    int4 d4 = reinterpret_cast<const int4*>(dst)[t];
    atomicAdd(&g_degi[d4.x], 1);
    atomicAdd(&g_degi[d4.y], 1);
    atomicAdd(&g_degi[d4.z], 1);
    atomicAdd(&g_degi[d4.w], 1);
}

// ---------------- single-pass decoupled-lookback scan + dis + cursor init ----------------
// state word: flag(<<32) | value.  flag: 0=empty, 1=aggregate, 2=inclusive prefix.
__global__ __launch_bounds__(256) void k_scan() {
    __shared__ int sm[256];
    __shared__ int s_off;
    int b = blockIdx.x, t = threadIdx.x;
    int i = b * 256 + t;
    int v = (i < N_NODES) ? g_degi[i] : 0;
    sm[t] = v;
    __syncthreads();
#pragma unroll
    for (int off = 1; off < 256; off <<= 1) {
        int u = (t >= off) ? sm[t - off] : 0;
        __syncthreads();
        if (t >= off) sm[t] += u;
        __syncthreads();
    }
    int incl = sm[t];
    int bsum = sm[255];

    if (t == 0) {
        unsigned long long w = (b == 0) ? ((2ull << 32) | (unsigned)bsum)
                                        : ((1ull << 32) | (unsigned)bsum);
        atomicExch(&g_state[b], w);
        if (b == 0) s_off = 0;
    }
    if (b > 0 && t < 32) {
        int jbase = b - 1;
        int acc = 0;
        while (true) {
            int j = jbase - t;
            unsigned long long w = (j >= 0) ? atomicAdd(&g_state[j], 0ull) : (2ull << 32);
            int flag = (int)(w >> 32);
            if (__ballot_sync(0xffffffffu, flag == 0)) continue;     // window not ready
            unsigned pmask = __ballot_sync(0xffffffffu, flag == 2);
            int val = (int)(w & 0xffffffffu);
            if (pmask) {
                int fl = __ffs(pmask) - 1;                            // nearest PREFIX lane
                if (t > fl) val = 0;
#pragma unroll
                for (int o = 16; o; o >>= 1) val += __shfl_xor_sync(0xffffffffu, val, o);
                acc += val;
                break;
            } else {                                                  // all AGG: take, slide
#pragma unroll
                for (int o = 16; o; o >>= 1) val += __shfl_xor_sync(0xffffffffu, val, o);
                acc += val;
                jbase -= 32;
            }
        }
        if (t == 0) {
            atomicExch(&g_state[b], (2ull << 32) | (unsigned)(acc + bsum));
            s_off = acc;
        }
    }
    __syncthreads();
    if (i < N_NODES) {
        int r = s_off + incl - v;      // exclusive prefix
        g_rowptr[i] = r;
        g_cursor[i] = r;
        g_dis[i] = rsqrtf((float)(g_degi[i] + 1));
    }
    if (b == SCAN_BLOCKS - 1 && t == 255) g_rowptr[N_NODES] = N_EDGES;
}

// ---------------- CSR fill ----------------
__global__ void k_fill(const int* __restrict__ src, const int* __restrict__ dst) {
    int e = blockIdx.x * blockDim.x + threadIdx.x;
    if (e >= N_EDGES) return;
    int d = dst[e];
    int s = src[e];
    int pos = atomicAdd(&g_cursor[d], 1);
    g_csrc[pos] = s;
    g_cw[pos] = g_dis[s] * g_dis[d];
}

// ---------------- gather, 64-col fp16 (layer 1): warp per node, 4-edge unroll ----------------
__global__ __launch_bounds__(256) void k_gather64() {
    int t = blockIdx.x * blockDim.x + threadIdx.x;
    int node = t >> 5;
    if (node >= N_NODES) return;
    int lane = t & 31;
    const unsigned* xs = reinterpret_cast<const unsigned*>(g_x16);

    int beg = g_rowptr[node], end = g_rowptr[node + 1];
    float dd = g_dis[node];
    float w0 = dd * dd;
    unsigned p = xs[(size_t)node * 32 + lane];
    float2 f = __half22float2(*reinterpret_cast<__half2*>(&p));
    float2 acc = make_float2(f.x * w0, f.y * w0);

    int i = beg;
    for (; i + 4 <= end; i += 4) {
        int s0 = g_csrc[i],     s1 = g_csrc[i + 1];
        int s2 = g_csrc[i + 2], s3 = g_csrc[i + 3];
        float wa = g_cw[i],     wb = g_cw[i + 1];
        float wc = g_cw[i + 2], wd = g_cw[i + 3];
        unsigned q0 = xs[(size_t)s0 * 32 + lane];
        unsigned q1 = xs[(size_t)s1 * 32 + lane];
        unsigned q2 = xs[(size_t)s2 * 32 + lane];
        unsigned q3 = xs[(size_t)s3 * 32 + lane];
        float2 a0 = __half22float2(*reinterpret_cast<__half2*>(&q0));
        float2 a1 = __half22float2(*reinterpret_cast<__half2*>(&q1));
        float2 a2 = __half22float2(*reinterpret_cast<__half2*>(&q2));
        float2 a3 = __half22float2(*reinterpret_cast<__half2*>(&q3));
        acc.x += a0.x * wa + a1.x * wb + a2.x * wc + a3.x * wd;
        acc.y += a0.y * wa + a1.y * wb + a2.y * wc + a3.y * wd;
    }
    for (; i < end; i++) {
        int s = g_csrc[i];
        float w = g_cw[i];
        unsigned q = xs[(size_t)s * 32 + lane];
        float2 a = __half22float2(*reinterpret_cast<__half2*>(&q));
        acc.x += a.x * w;
        acc.y += a.y * w;
    }
    reinterpret_cast<__half2*>(g_agg16)[(size_t)node * 32 + lane] = __floats2half2_rn(acc.x, acc.y);
}

// ---------------- gather, 128-col fp16 (layer 2): warp per node, 4-edge unroll ----------------
__global__ __launch_bounds__(256) void k_gather128() {
    int t = blockIdx.x * blockDim.x + threadIdx.x;
    int node = t >> 5;
    if (node >= N_NODES) return;
    int lane = t & 31;
    const uint2* hs = reinterpret_cast<const uint2*>(g_h16);

    int beg = g_rowptr[node], end = g_rowptr[node + 1];
    float dd = g_dis[node];
    float w0 = dd * dd;
    uint2 p = hs[(size_t)node * 32 + lane];
    float2 fa = __half22float2(*reinterpret_cast<__half2*>(&p.x));
    float2 fb = __half22float2(*reinterpret_cast<__half2*>(&p.y));
    float4 acc = make_float4(fa.x * w0, fa.y * w0, fb.x * w0, fb.y * w0);

    int i = beg;
    for (; i + 4 <= end; i += 4) {
        int s0 = g_csrc[i],     s1 = g_csrc[i + 1];
        int s2 = g_csrc[i + 2], s3 = g_csrc[i + 3];
        float wa = g_cw[i],     wb = g_cw[i + 1];
        float wc = g_cw[i + 2], wd = g_cw[i + 3];
        uint2 q0 = hs[(size_t)s0 * 32 + lane];
        uint2 q1 = hs[(size_t)s1 * 32 + lane];
        uint2 q2 = hs[(size_t)s2 * 32 + lane];
        uint2 q3 = hs[(size_t)s3 * 32 + lane];
        float2 a0 = __half22float2(*reinterpret_cast<__half2*>(&q0.x));
        float2 b0 = __half22float2(*reinterpret_cast<__half2*>(&q0.y));
        float2 a1 = __half22float2(*reinterpret_cast<__half2*>(&q1.x));
        float2 b1 = __half22float2(*reinterpret_cast<__half2*>(&q1.y));
        float2 a2 = __half22float2(*reinterpret_cast<__half2*>(&q2.x));
        float2 b2 = __half22float2(*reinterpret_cast<__half2*>(&q2.y));
        float2 a3 = __half22float2(*reinterpret_cast<__half2*>(&q3.x));
        float2 b3 = __half22float2(*reinterpret_cast<__half2*>(&q3.y));
        acc.x += a0.x * wa + a1.x * wb + a2.x * wc + a3.x * wd;
        acc.y += a0.y * wa + a1.y * wb + a2.y * wc + a3.y * wd;
        acc.z += b0.x * wa + b1.x * wb + b2.x * wc + b3.x * wd;
        acc.w += b0.y * wa + b1.y * wb + b2.y * wc + b3.y * wd;
    }
    for (; i < end; i++) {
        int s = g_csrc[i];
        float w = g_cw[i];
        uint2 q = hs[(size_t)s * 32 + lane];
        float2 a = __half22float2(*reinterpret_cast<__half2*>(&q.x));
        float2 b = __half22float2(*reinterpret_cast<__half2*>(&q.y));
        acc.x += a.x * w; acc.y += a.y * w;
        acc.z += b.x * w; acc.w += b.y * w;
    }
    __half2 h0 = __floats2half2_rn(acc.x, acc.y);
    __half2 h1 = __floats2half2_rn(acc.z, acc.w);
    unsigned u0 = *reinterpret_cast<unsigned*>(&h0);
    unsigned u1 = *reinterpret_cast<unsigned*>(&h1);
    reinterpret_cast<uint2*>(g_agg16)[(size_t)node * 32 + lane] = make_uint2(u0, u1);
}

// ---------------- tensor-core GEMM: out = relu(agg16[M x K] @ W16[K x 128] + bias) ----------------
template <int K, bool H16OUT>
__global__ __launch_bounds__(128) void k_gemm_mma(const float* __restrict__ bias) {
    const __half* W16 = H16OUT ? g_w16a : g_w16b;   // layer1 -> W1, layer2 -> W2
    constexpr int LDA = K + 8;
    constexpr int LDW = 64 + 8;
    __shared__ __half As[64 * LDA];
    __shared__ __half Ws[K * LDW];

    const int tid  = threadIdx.x;
    const int lane = tid & 31;
    const int w    = tid >> 5;
    const int row0 = blockIdx.x * 64;

    {
        constexpr int RV = K / 8;
        for (int idx = tid; idx < 64 * RV; idx += 128) {
            int r = idx / RV, c = idx - r * RV;
            uint4 v = make_uint4(0u, 0u, 0u, 0u);
            int row = row0 + r;
            if (row < N_NODES)
                v = reinterpret_cast<const uint4*>(g_agg16)[(size_t)row * RV + c];
            *reinterpret_cast<uint4*>(&As[r * LDA + c * 8]) = v;
        }
    }

    float acc[16][4];
#pragma unroll
    for (int nt = 0; nt < 16; nt++)
#pragma unroll
        for (int j = 0; j < 4; j++) acc[nt][j] = 0.0f;

#pragma unroll
    for (int h = 0; h < 2; h++) {
        __syncthreads();
        {
            constexpr int RV = 64 / 8;
            for (int idx = tid; idx < K * RV; idx += 128) {
                int r = idx / RV, c = idx - r * RV;
                uint4 v = reinterpret_cast<const uint4*>(W16 + (size_t)r * HID + h * 64)[c];
                *reinterpret_cast<uint4*>(&Ws[r * LDW + c * 8]) = v;
            }
        }
        __syncthreads();

#pragma unroll
        for (int ks = 0; ks < K / 16; ks++) {
            unsigned a0, a1, a2, a3;
            {
                int tile = lane >> 3, lrow = lane & 7;
                int arow = w * 16 + (tile & 1) * 8 + lrow;
                int acol = ks * 16 + (tile >> 1) * 8;
                unsigned addr = (unsigned)__cvta_generic_to_shared(&As[arow * LDA + acol]);
                asm volatile("ldmatrix.sync.aligned.m8n8.x4.shared.b16 {%0,%1,%2,%3}, [%4];"
                             : "=r"(a0), "=r"(a1), "=r"(a2), "=r"(a3) : "r"(addr));
            }
#pragma unroll
            for (int nt = 0; nt < 8; nt++) {
                unsigned b0, b1;
                {
                    int l = lane & 15;
                    int krow = ks * 16 + l;
                    unsigned addr = (unsigned)__cvta_generic_to_shared(&Ws[krow * LDW + nt * 8]);
                    asm volatile("ldmatrix.sync.aligned.m8n8.x2.trans.shared.b16 {%0,%1}, [%2];"
                                 : "=r"(b0), "=r"(b1) : "r"(addr));
                }
                float* a4 = acc[h * 8 + nt];
                asm volatile("mma.sync.aligned.m16n8k16.row.col.f32.f16.f16.f32 "
                             "{%0,%1,%2,%3}, {%4,%5,%6,%7}, {%8,%9}, {%0,%1,%2,%3};"
                             : "+f"(a4[0]), "+f"(a4[1]), "+f"(a4[2]), "+f"(a4[3])
                             : "r"(a0), "r"(a1), "r"(a2), "r"(a3), "r"(b0), "r"(b1));
            }
        }
    }

    int g  = lane >> 2;
    int tq = lane & 3;
    int ra = row0 + w * 16 + g;
    int rb = ra + 8;
#pragma unroll
    for (int nt = 0; nt < 16; nt++) {
        int col = nt * 8 + tq * 2;
        float bv0 = bias[col], bv1 = bias[col + 1];
        float v0 = fmaxf(acc[nt][0] + bv0, 0.0f);
        float v1 = fmaxf(acc[nt][1] + bv1, 0.0f);
        float v2 = fmaxf(acc[nt][2] + bv0, 0.0f);
        float v3 = fmaxf(acc[nt][3] + bv1, 0.0f);
        if (H16OUT) {
            if (ra < N_NODES)
                *reinterpret_cast<__half2*>(&g_h16[(size_t)ra * HID + col]) = __floats2half2_rn(v0, v1);
            if (rb < N_NODES)
                *reinterpret_cast<__half2*>(&g_h16[(size_t)rb * HID + col]) = __floats2half2_rn(v2, v3);
        } else {
            if (ra < N_NODES)
                *reinterpret_cast<float2*>(&g_bufA[(size_t)ra * HID + col]) = make_float2(v0, v1);
            if (rb < N_NODES)
                *reinterpret_cast<float2*>(&g_bufA[(size_t)rb * HID + col]) = make_float2(v2, v3);
        }
    }
}

// ---------------- pooling: run-length over sorted batch ----------------
// block = 128 threads (one per column), 32 consecutive nodes per block.
__global__ __launch_bounds__(128) void k_pool(const int* __restrict__ batch) {
    int n0 = blockIdx.x * 32;
    if (n0 >= N_NODES) return;
    int t = threadIdx.x;
    int nmax = N_NODES - n0; if (nmax > 32) nmax = 32;

    float acc = 0.0f;
    int curb = batch[n0];
    int runlen = 0;
    for (int k = 0; k < nmax; k++) {
        int node = n0 + k;
        int bb = batch[node];
        if (bb != curb) {
            atomicAdd(&g_pooled[curb * HID + t], acc);
            if (t == 0) atomicAdd(&g_cnt[curb], (float)runlen);
            acc = 0.0f; runlen = 0; curb = bb;
        }
        acc += g_bufA[(size_t)node * HID + t];
        runlen++;
    }
    atomicAdd(&g_pooled[curb * HID + t], acc);
    if (t == 0) atomicAdd(&g_cnt[curb], (float)runlen);
}

// ---------------- head ----------------
__global__ __launch_bounds__(128) void k_head(const float* __restrict__ W3,
                                              const float* __restrict__ b3,
                                              const float* __restrict__ W4,
                                              const float* __restrict__ b4,
                                              float* __restrict__ out) {
    __shared__ float mean[HID];
    __shared__ float y[HID];
    int b = blockIdx.x;
    int t = threadIdx.x;
    float c = fmaxf(g_cnt[b], 1.0f);
    mean[t] = g_pooled[b * HID + t] / c;
    __syncthreads();

    float acc = b3[t];
#pragma unroll 8
    for (int k = 0; k < HID; k++) acc += mean[k] * W3[k * HID + t];
    y[t] = fmaxf(acc, 0.0f);
    __syncthreads();

    if (t < OUT_DIM) {
        float acc2 = b4[t];
#pragma unroll 8
        for (int k = 0; k < HID; k++) acc2 += y[k] * W4[k * OUT_DIM + t];
        out[b * OUT_DIM + t] = acc2;
    }
}

// ---------------- launch ----------------
extern "C" void kernel_launch(void* const* d_in, const int* in_sizes, int n_in,
                              void* d_out, int out_size) {
    const float* x     = (const float*)d_in[0];
    const int*   ei    = (const int*)d_in[1];
    const int*   batch = (const int*)d_in[2];
    const float* W1 = (const float*)d_in[3];
    const float* b1 = (const float*)d_in[4];
    const float* W2 = (const float*)d_in[5];
    const float* b2 = (const float*)d_in[6];
    const float* W3 = (const float*)d_in[7];
    const float* b3 = (const float*)d_in[8];
    const float* W4 = (const float*)d_in[9];
    const float* b4 = (const float*)d_in[10];
    float* out = (float*)d_out;

    const int* src = ei;
    const int* dst = ei + N_EDGES;

    // prelude + CSR build (scan is one decoupled-lookback kernel)
    k_prelude<<<(N_NODES * (IN_DIM / 2) + 255) / 256, 256>>>(x, W1, W2);
    k_deg<<<(N_EDGES / 4 + 255) / 256, 256>>>(dst);
    k_scan<<<SCAN_BLOCKS, 256>>>();
    k_fill<<<(N_EDGES + 255) / 256, 256>>>(src, dst);

    // layer 1: gather x16 -> agg16, tensor GEMM (W1) -> h16 (fp16)
    k_gather64<<<(N_NODES * 32 + 255) / 256, 256>>>();
    k_gemm_mma<IN_DIM, true><<<(N_NODES + 63) / 64, 128>>>(b1);

    // layer 2: gather h16 -> agg16, tensor GEMM (W2) -> bufA (fp32)
    k_gather128<<<(N_NODES * 32 + 255) / 256, 256>>>();
    k_gemm_mma<HID, false><<<(N_NODES + 63) / 64, 128>>>(b2);

    // pool (run-length, sorted batch) + head
    k_pool<<<(N_NODES + 31) / 32, 128>>>(batch);
    k_head<<<NB, 128>>>(W3, b3, W4, b4, out);
}

// round 17
// speedup vs baseline: 2.7680x; 1.1161x over previous
#include <cuda_runtime.h>
#include <cuda_fp16.h>
#include <math.h>

#define N_NODES 50000
#define N_EDGES 800000
#define NB      64
#define IN_DIM  64
#define HID     128
#define OUT_DIM 64
#define SCAN_BLOCKS 196   // 196*256 = 50176 >= N_NODES

// ---------------- scratch (device globals: no allocs allowed) ----------------
__device__ __align__(16) int    g_degi[N_NODES];
__device__ __align__(16) float  g_dis[N_NODES];
__device__ __align__(16) int    g_rowptr[N_NODES + 1];
__device__ __align__(16) int    g_cursor[N_NODES];
__device__ __align__(16) int    g_csrc[N_EDGES];
__device__ __align__(16) unsigned long long g_state[SCAN_BLOCKS];  // lookback state
__device__ __align__(16) __half g_x16[(size_t)N_NODES * IN_DIM];   // fp16 x * dis  (pre-scaled)
__device__ __align__(16) __half g_h16[(size_t)N_NODES * HID];      // fp16 relu(h1) * dis
__device__ __align__(16) __half g_agg16[(size_t)N_NODES * HID];    // fp16 aggregated (GEMM A input)
__device__ __align__(16) __half g_w16a[IN_DIM * HID];              // fp16 W1
__device__ __align__(16) __half g_w16b[HID * HID];                 // fp16 W2
__device__ __align__(16) float  g_bufA[(size_t)N_NODES * HID];     // layer-2 GEMM out (fp32)
__device__ __align__(16) float  g_pooled[NB * HID];
__device__ __align__(16) float  g_cnt[NB];

// ---------------- fused prelude: zeros + W->fp16 ----------------
__global__ void k_prelude(const float* __restrict__ W1, const float* __restrict__ W2) {
    int t = blockIdx.x * blockDim.x + threadIdx.x;
    if (t < N_NODES) g_degi[t] = 0;
    if (t < NB * HID) g_pooled[t] = 0.0f;
    if (t < NB) g_cnt[t] = 0.0f;
    if (t < SCAN_BLOCKS) g_state[t] = 0ull;
    if (t < IN_DIM * HID) g_w16a[t] = __float2half_rn(W1[t]);
    if (t < HID * HID)    g_w16b[t] = __float2half_rn(W2[t]);
}

// ---------------- degree counts over dst: int4, 4 edges/thread ----------------
__global__ void k_deg(const int* __restrict__ dst) {
    int t = blockIdx.x * blockDim.x + threadIdx.x;
    if (t >= N_EDGES / 4) return;
    int4 d4 = reinterpret_cast<const int4*>(dst)[t];
    atomicAdd(&g_degi[d4.x], 1);
    atomicAdd(&g_degi[d4.y], 1);
    atomicAdd(&g_degi[d4.z], 1);
    atomicAdd(&g_degi[d4.w], 1);
}

// ---------------- single-pass decoupled-lookback scan + dis + cursor init ----------------
__global__ __launch_bounds__(256) void k_scan() {
    __shared__ int sm[256];
    __shared__ int s_off;
    int b = blockIdx.x, t = threadIdx.x;
    int i = b * 256 + t;
    int v = (i < N_NODES) ? g_degi[i] : 0;
    sm[t] = v;
    __syncthreads();
#pragma unroll
    for (int off = 1; off < 256; off <<= 1) {
        int u = (t >= off) ? sm[t - off] : 0;
        __syncthreads();
        if (t >= off) sm[t] += u;
        __syncthreads();
    }
    int incl = sm[t];
    int bsum = sm[255];

    if (t == 0) {
        unsigned long long w = (b == 0) ? ((2ull << 32) | (unsigned)bsum)
                                        : ((1ull << 32) | (unsigned)bsum);
        atomicExch(&g_state[b], w);
        if (b == 0) s_off = 0;
    }
    if (b > 0 && t < 32) {
        int jbase = b - 1;
        int acc = 0;
        while (true) {
            int j = jbase - t;
            unsigned long long w = (j >= 0) ? atomicAdd(&g_state[j], 0ull) : (2ull << 32);
            int flag = (int)(w >> 32);
            if (__ballot_sync(0xffffffffu, flag == 0)) continue;
            unsigned pmask = __ballot_sync(0xffffffffu, flag == 2);
            int val = (int)(w & 0xffffffffu);
            if (pmask) {
                int fl = __ffs(pmask) - 1;
                if (t > fl) val = 0;
#pragma unroll
                for (int o = 16; o; o >>= 1) val += __shfl_xor_sync(0xffffffffu, val, o);
                acc += val;
                break;
            } else {
#pragma unroll
                for (int o = 16; o; o >>= 1) val += __shfl_xor_sync(0xffffffffu, val, o);
                acc += val;
                jbase -= 32;
            }
        }
        if (t == 0) {
            atomicExch(&g_state[b], (2ull << 32) | (unsigned)(acc + bsum));
            s_off = acc;
        }
    }
    __syncthreads();
    if (i < N_NODES) {
        int r = s_off + incl - v;
        g_rowptr[i] = r;
        g_cursor[i] = r;
        g_dis[i] = rsqrtf((float)(g_degi[i] + 1));
    }
    if (b == SCAN_BLOCKS - 1 && t == 255) g_rowptr[N_NODES] = N_EDGES;
}

// ---------------- fused CSR fill (csrc only) + x scale/convert ----------------
// grid covers N_NODES*32 (xscale); first N_EDGES/4 threads also do fill.
__global__ void k_fill_xscale(const float* __restrict__ x,
                              const int* __restrict__ src, const int* __restrict__ dst) {
    int t = blockIdx.x * blockDim.x + threadIdx.x;
    if (t < N_NODES * (IN_DIM / 2)) {
        int node = t >> 5;                       // 32 half2 per node
        float d = g_dis[node];
        float2 v = reinterpret_cast<const float2*>(x)[t];
        reinterpret_cast<__half2*>(g_x16)[t] = __floats2half2_rn(v.x * d, v.y * d);
    }
    if (t < N_EDGES / 4) {
        int4 s4 = reinterpret_cast<const int4*>(src)[t];
        int4 d4 = reinterpret_cast<const int4*>(dst)[t];
        g_csrc[atomicAdd(&g_cursor[d4.x], 1)] = s4.x;
        g_csrc[atomicAdd(&g_cursor[d4.y], 1)] = s4.y;
        g_csrc[atomicAdd(&g_cursor[d4.z], 1)] = s4.z;
        g_csrc[atomicAdd(&g_cursor[d4.w], 1)] = s4.w;
    }
}

// ---------------- gather, 64-col fp16 (layer 1): warp per node, weightless adds ----------------
__global__ __launch_bounds__(256) void k_gather64() {
    int t = blockIdx.x * blockDim.x + threadIdx.x;
    int node = t >> 5;
    if (node >= N_NODES) return;
    int lane = t & 31;
    const unsigned* xs = reinterpret_cast<const unsigned*>(g_x16);

    int beg = g_rowptr[node], end = g_rowptr[node + 1];
    unsigned p = xs[(size_t)node * 32 + lane];          // self term (pre-scaled)
    float2 f = __half22float2(*reinterpret_cast<__half2*>(&p));
    float2 acc = f;

    int i = beg;
    for (; i + 4 <= end; i += 4) {
        int s0 = g_csrc[i],     s1 = g_csrc[i + 1];
        int s2 = g_csrc[i + 2], s3 = g_csrc[i + 3];
        unsigned q0 = xs[(size_t)s0 * 32 + lane];
        unsigned q1 = xs[(size_t)s1 * 32 + lane];
        unsigned q2 = xs[(size_t)s2 * 32 + lane];
        unsigned q3 = xs[(size_t)s3 * 32 + lane];
        float2 a0 = __half22float2(*reinterpret_cast<__half2*>(&q0));
        float2 a1 = __half22float2(*reinterpret_cast<__half2*>(&q1));
        float2 a2 = __half22float2(*reinterpret_cast<__half2*>(&q2));
        float2 a3 = __half22float2(*reinterpret_cast<__half2*>(&q3));
        acc.x += (a0.x + a1.x) + (a2.x + a3.x);
        acc.y += (a0.y + a1.y) + (a2.y + a3.y);
    }
    for (; i < end; i++) {
        int s = g_csrc[i];
        unsigned q = xs[(size_t)s * 32 + lane];
        float2 a = __half22float2(*reinterpret_cast<__half2*>(&q));
        acc.x += a.x;
        acc.y += a.y;
    }
    float dd = g_dis[node];
    reinterpret_cast<__half2*>(g_agg16)[(size_t)node * 32 + lane] =
        __floats2half2_rn(acc.x * dd, acc.y * dd);
}

// ---------------- gather, 128-col fp16 (layer 2): warp per node, weightless adds ----------------
__global__ __launch_bounds__(256) void k_gather128() {
    int t = blockIdx.x * blockDim.x + threadIdx.x;
    int node = t >> 5;
    if (node >= N_NODES) return;
    int lane = t & 31;
    const uint2* hs = reinterpret_cast<const uint2*>(g_h16);

    int beg = g_rowptr[node], end = g_rowptr[node + 1];
    uint2 p = hs[(size_t)node * 32 + lane];             // self term (pre-scaled)
    float2 fa = __half22float2(*reinterpret_cast<__half2*>(&p.x));
    float2 fb = __half22float2(*reinterpret_cast<__half2*>(&p.y));
    float4 acc = make_float4(fa.x, fa.y, fb.x, fb.y);

    int i = beg;
    for (; i + 4 <= end; i += 4) {
        int s0 = g_csrc[i],     s1 = g_csrc[i + 1];
        int s2 = g_csrc[i + 2], s3 = g_csrc[i + 3];
        uint2 q0 = hs[(size_t)s0 * 32 + lane];
        uint2 q1 = hs[(size_t)s1 * 32 + lane];
        uint2 q2 = hs[(size_t)s2 * 32 + lane];
        uint2 q3 = hs[(size_t)s3 * 32 + lane];
        float2 a0 = __half22float2(*reinterpret_cast<__half2*>(&q0.x));
        float2 b0 = __half22float2(*reinterpret_cast<__half2*>(&q0.y));
        float2 a1 = __half22float2(*reinterpret_cast<__half2*>(&q1.x));
        float2 b1 = __half22float2(*reinterpret_cast<__half2*>(&q1.y));
        float2 a2 = __half22float2(*reinterpret_cast<__half2*>(&q2.x));
        float2 b2 = __half22float2(*reinterpret_cast<__half2*>(&q2.y));
        float2 a3 = __half22float2(*reinterpret_cast<__half2*>(&q3.x));
        float2 b3 = __half22float2(*reinterpret_cast<__half2*>(&q3.y));
        acc.x += (a0.x + a1.x) + (a2.x + a3.x);
        acc.y += (a0.y + a1.y) + (a2.y + a3.y);
        acc.z += (b0.x + b1.x) + (b2.x + b3.x);
        acc.w += (b0.y + b1.y) + (b2.y + b3.y);
    }
    for (; i < end; i++) {
        int s = g_csrc[i];
        uint2 q = hs[(size_t)s * 32 + lane];
        float2 a = __half22float2(*reinterpret_cast<__half2*>(&q.x));
        float2 b = __half22float2(*reinterpret_cast<__half2*>(&q.y));
        acc.x += a.x; acc.y += a.y;
        acc.z += b.x; acc.w += b.y;
    }
    float dd = g_dis[node];
    __half2 h0 = __floats2half2_rn(acc.x * dd, acc.y * dd);
    __half2 h1 = __floats2half2_rn(acc.z * dd, acc.w * dd);
    unsigned u0 = *reinterpret_cast<unsigned*>(&h0);
    unsigned u1 = *reinterpret_cast<unsigned*>(&h1);
    reinterpret_cast<uint2*>(g_agg16)[(size_t)node * 32 + lane] = make_uint2(u0, u1);
}

// ---------------- tensor-core GEMM: out = relu(agg16[M x K] @ W16[K x 128] + bias) ----------------
// H16OUT: store fp16 h16 pre-scaled by dis[row] (feeds gather128); else fp32 bufA.
template <int K, bool H16OUT>
__global__ __launch_bounds__(128) void k_gemm_mma(const float* __restrict__ bias) {
    const __half* W16 = H16OUT ? g_w16a : g_w16b;
    constexpr int LDA = K + 8;
    constexpr int LDW = 64 + 8;
    __shared__ __half As[64 * LDA];
    __shared__ __half Ws[K * LDW];

    const int tid  = threadIdx.x;
    const int lane = tid & 31;
    const int w    = tid >> 5;
    const int row0 = blockIdx.x * 64;

    {
        constexpr int RV = K / 8;
        for (int idx = tid; idx < 64 * RV; idx += 128) {
            int r = idx / RV, c = idx - r * RV;
            uint4 v = make_uint4(0u, 0u, 0u, 0u);
            int row = row0 + r;
            if (row < N_NODES)
                v = reinterpret_cast<const uint4*>(g_agg16)[(size_t)row * RV + c];
            *reinterpret_cast<uint4*>(&As[r * LDA + c * 8]) = v;
        }
    }

    float acc[16][4];
#pragma unroll
    for (int nt = 0; nt < 16; nt++)
#pragma unroll
        for (int j = 0; j < 4; j++) acc[nt][j] = 0.0f;

#pragma unroll
    for (int h = 0; h < 2; h++) {
        __syncthreads();
        {
            constexpr int RV = 64 / 8;
            for (int idx = tid; idx < K * RV; idx += 128) {
                int r = idx / RV, c = idx - r * RV;
                uint4 v = reinterpret_cast<const uint4*>(W16 + (size_t)r * HID + h * 64)[c];
                *reinterpret_cast<uint4*>(&Ws[r * LDW + c * 8]) = v;
            }
        }
        __syncthreads();

#pragma unroll
        for (int ks = 0; ks < K / 16; ks++) {
            unsigned a0, a1, a2, a3;
            {
                int tile = lane >> 3, lrow = lane & 7;
                int arow = w * 16 + (tile & 1) * 8 + lrow;
                int acol = ks * 16 + (tile >> 1) * 8;
                unsigned addr = (unsigned)__cvta_generic_to_shared(&As[arow * LDA + acol]);
                asm volatile("ldmatrix.sync.aligned.m8n8.x4.shared.b16 {%0,%1,%2,%3}, [%4];"
                             : "=r"(a0), "=r"(a1), "=r"(a2), "=r"(a3) : "r"(addr));
            }
#pragma unroll
            for (int nt = 0; nt < 8; nt++) {
                unsigned b0, b1;
                {
                    int l = lane & 15;
                    int krow = ks * 16 + l;
                    unsigned addr = (unsigned)__cvta_generic_to_shared(&Ws[krow * LDW + nt * 8]);
                    asm volatile("ldmatrix.sync.aligned.m8n8.x2.trans.shared.b16 {%0,%1}, [%2];"
                                 : "=r"(b0), "=r"(b1) : "r"(addr));
                }
                float* a4 = acc[h * 8 + nt];
                asm volatile("mma.sync.aligned.m16n8k16.row.col.f32.f16.f16.f32 "
                             "{%0,%1,%2,%3}, {%4,%5,%6,%7}, {%8,%9}, {%0,%1,%2,%3};"
                             : "+f"(a4[0]), "+f"(a4[1]), "+f"(a4[2]), "+f"(a4[3])
                             : "r"(a0), "r"(a1), "r"(a2), "r"(a3), "r"(b0), "r"(b1));
            }
        }
    }

    int g  = lane >> 2;
    int tq = lane & 3;
    int ra = row0 + w * 16 + g;
    int rb = ra + 8;
    float da = 1.0f, db = 1.0f;
    if (H16OUT) {
        da = (ra < N_NODES) ? g_dis[ra] : 0.0f;
        db = (rb < N_NODES) ? g_dis[rb] : 0.0f;
    }
#pragma unroll
    for (int nt = 0; nt < 16; nt++) {
        int col = nt * 8 + tq * 2;
        float bv0 = bias[col], bv1 = bias[col + 1];
        float v0 = fmaxf(acc[nt][0] + bv0, 0.0f);
        float v1 = fmaxf(acc[nt][1] + bv1, 0.0f);
        float v2 = fmaxf(acc[nt][2] + bv0, 0.0f);
        float v3 = fmaxf(acc[nt][3] + bv1, 0.0f);
        if (H16OUT) {
            if (ra < N_NODES)
                *reinterpret_cast<__half2*>(&g_h16[(size_t)ra * HID + col]) =
                    __floats2half2_rn(v0 * da, v1 * da);
            if (rb < N_NODES)
                *reinterpret_cast<__half2*>(&g_h16[(size_t)rb * HID + col]) =
                    __floats2half2_rn(v2 * db, v3 * db);
        } else {
            if (ra < N_NODES)
                *reinterpret_cast<float2*>(&g_bufA[(size_t)ra * HID + col]) = make_float2(v0, v1);
            if (rb < N_NODES)
                *reinterpret_cast<float2*>(&g_bufA[(size_t)rb * HID + col]) = make_float2(v2, v3);
        }
    }
}

// ---------------- pooling: run-length over sorted batch ----------------
__global__ __launch_bounds__(128) void k_pool(const int* __restrict__ batch) {
    int n0 = blockIdx.x * 32;
    if (n0 >= N_NODES) return;
    int t = threadIdx.x;
    int nmax = N_NODES - n0; if (nmax > 32) nmax = 32;

    float acc = 0.0f;
    int curb = batch[n0];
    int runlen = 0;
    for (int k = 0; k < nmax; k++) {
        int node = n0 + k;
        int bb = batch[node];
        if (bb != curb) {
            atomicAdd(&g_pooled[curb * HID + t], acc);
            if (t == 0) atomicAdd(&g_cnt[curb], (float)runlen);
            acc = 0.0f; runlen = 0; curb = bb;
        }
        acc += g_bufA[(size_t)node * HID + t];
        runlen++;
    }
    atomicAdd(&g_pooled[curb * HID + t], acc);
    if (t == 0) atomicAdd(&g_cnt[curb], (float)runlen);
}

// ---------------- head ----------------
__global__ __launch_bounds__(128) void k_head(const float* __restrict__ W3,
                                              const float* __restrict__ b3,
                                              const float* __restrict__ W4,
                                              const float* __restrict__ b4,
                                              float* __restrict__ out) {
    __shared__ float mean[HID];
    __shared__ float y[HID];
    int b = blockIdx.x;
    int t = threadIdx.x;
    float c = fmaxf(g_cnt[b], 1.0f);
    mean[t] = g_pooled[b * HID + t] / c;
    __syncthreads();

    float acc = b3[t];
#pragma unroll 8
    for (int k = 0; k < HID; k++) acc += mean[k] * W3[k * HID + t];
    y[t] = fmaxf(acc, 0.0f);
    __syncthreads();

    if (t < OUT_DIM) {
        float acc2 = b4[t];
#pragma unroll 8
        for (int k = 0; k < HID; k++) acc2 += y[k] * W4[k * OUT_DIM + t];
        out[b * OUT_DIM + t] = acc2;
    }
}

// ---------------- launch ----------------
extern "C" void kernel_launch(void* const* d_in, const int* in_sizes, int n_in,
                              void* d_out, int out_size) {
    const float* x     = (const float*)d_in[0];
    const int*   ei    = (const int*)d_in[1];
    const int*   batch = (const int*)d_in[2];
    const float* W1 = (const float*)d_in[3];
    const float* b1 = (const float*)d_in[4];
    const float* W2 = (const float*)d_in[5];
    const float* b2 = (const float*)d_in[6];
    const float* W3 = (const float*)d_in[7];
    const float* b3 = (const float*)d_in[8];
    const float* W4 = (const float*)d_in[9];
    const float* b4 = (const float*)d_in[10];
    float* out = (float*)d_out;

    const int* src = ei;
    const int* dst = ei + N_EDGES;

    // prelude + CSR build (fill fused with x scale/convert)
    k_prelude<<<(N_NODES + 255) / 256, 256>>>(W1, W2);
    k_deg<<<(N_EDGES / 4 + 255) / 256, 256>>>(dst);
    k_scan<<<SCAN_BLOCKS, 256>>>();
    k_fill_xscale<<<(N_NODES * (IN_DIM / 2) + 255) / 256, 256>>>(x, src, dst);

    // layer 1: gather x16 -> agg16, tensor GEMM (W1) -> h16 (fp16, dis-scaled)
    k_gather64<<<(N_NODES * 32 + 255) / 256, 256>>>();
    k_gemm_mma<IN_DIM, true><<<(N_NODES + 63) / 64, 128>>>(b1);

    // layer 2: gather h16 -> agg16, tensor GEMM (W2) -> bufA (fp32)
    k_gather128<<<(N_NODES * 32 + 255) / 256, 256>>>();
    k_gemm_mma<HID, false><<<(N_NODES + 63) / 64, 128>>>(b2);

    // pool (run-length, sorted batch) + head
    k_pool<<<(N_NODES + 31) / 32, 128>>>(batch);
    k_head<<<NB, 128>>>(W3, b3, W4, b4, out);
}